// round 13
// baseline (speedup 1.0000x reference)
#include <cuda_runtime.h>
#include <cuda_fp16.h>
#include <mma.h>
#include <cstdint>
using namespace nvcuda;

#define N_NODES 50000
#define N_EDGES 800000
#define IN_F    32
#define HF      128   // H*F
#define NH      4
#define FD      32
#define G3      96    // 3*F

// ---------------- scratch (device globals) ------------------------------------
__device__ __align__(16) __half g_feat[N_NODES * HF];  // fp16 gather stream
__device__ __align__(16) float  g_el  [N_NODES * NH];
__device__ __align__(16) float  g_er  [N_NODES * NH];
__device__ __align__(16) __half g_xh  [N_NODES * HF];  // GRU input, fp16
__device__ int g_cnt [N_NODES];
__device__ int g_rowp[N_NODES + 1];
__device__ int g_csrc[N_EDGES];

__device__ __forceinline__ float lrelu(float x) { return x > 0.f ? x : 0.2f * x; }
__device__ __forceinline__ float tanhfast(float x) {
    float y; asm("tanh.approx.f32 %0, %1;" : "=f"(y) : "f"(x)); return y;
}
// per-block int64-vs-int32 probe: int64 node ids < 2^31 have zero odd words
__device__ __forceinline__ int probe64(const void* idxbuf) {
    unsigned any = 0;
    const unsigned* raw = (const unsigned*)idxbuf;
#pragma unroll
    for (int k = 1; k < 64; k += 2) any |= raw[k];
    return any == 0u;
}

// ---------------- K1: feat-GEMM (reg-cached W col) + el/er + dst histogram -----
#define FEAT_BLOCKS 391   // ceil(50000/128)
__global__ void __launch_bounds__(256) k_feathist(
    const float* __restrict__ h, const float* __restrict__ Wg,
    const float* __restrict__ al, const float* __restrict__ ar,
    const void* __restrict__ dst)
{
    __shared__ float hsm[128 * IN_F];   // 16 KB
    __shared__ float sWlr[IN_F * 8];
    __shared__ int s64;
    int t = threadIdx.x;
    if (blockIdx.x >= FEAT_BLOCKS) {
        // histogram: 4 edges per thread, vectorized index loads
        if (t == 0) s64 = probe64(dst);
        __syncthreads();
        int is64 = s64;
        int e4 = ((blockIdx.x - FEAT_BLOCKS) * 256 + t) * 4;
        if (e4 >= N_EDGES) return;
        int d0, d1, d2, d3;
        if (is64) {
            longlong2 a = ((const longlong2*)dst)[e4 >> 1];
            longlong2 b = ((const longlong2*)dst)[(e4 >> 1) + 1];
            d0 = (int)a.x; d1 = (int)a.y; d2 = (int)b.x; d3 = (int)b.y;
        } else {
            int4 v = ((const int4*)dst)[e4 >> 2];
            d0 = v.x; d1 = v.y; d2 = v.z; d3 = v.w;
        }
        atomicAdd(&g_cnt[d0], 1); atomicAdd(&g_cnt[d1], 1);
        atomicAdd(&g_cnt[d2], 1); atomicAdd(&g_cnt[d3], 1);
        return;
    }
    // feat part: 128 nodes per block; thread owns output column tc for 64 nodes
    int tc = t & 127, half = t >> 7;
    float wreg[IN_F];
#pragma unroll
    for (int k = 0; k < IN_F; k++) wreg[k] = Wg[k * HF + tc];
    {   // per-block attn projection: sWlr[k*8+c] = sum_f Wg[k][hh*32+f]*a{l,r}[hh*32+f]
        int k = t >> 3, c = t & 7;
        const float* av = (c < 4) ? al : ar;
        int hh = c & 3;
        float s = 0.f;
#pragma unroll
        for (int f = 0; f < 32; f++)
            s = fmaf(Wg[k * HF + hh * 32 + f], av[hh * 32 + f], s);
        sWlr[t] = s;
    }
    int nb = blockIdx.x * 128;
    for (int i = t; i < 128 * IN_F; i += 256) {
        int n = nb + (i >> 5);
        hsm[i] = (n < N_NODES) ? h[n * IN_F + (i & 31)] : 0.0f;
    }
    __syncthreads();
    int lbase = half * 64;
    int jmax = min(64, N_NODES - nb - lbase);
    for (int j = 0; j < jmax; j++) {
        const float4* hrow = (const float4*)&hsm[(lbase + j) * IN_F];
        float a0 = 0.f, a1 = 0.f, a2 = 0.f, a3 = 0.f;
#pragma unroll
        for (int kk = 0; kk < IN_F / 4; kk++) {
            float4 hv = hrow[kk];
            a0 = fmaf(hv.x, wreg[4 * kk + 0], a0);
            a1 = fmaf(hv.y, wreg[4 * kk + 1], a1);
            a2 = fmaf(hv.z, wreg[4 * kk + 2], a2);
            a3 = fmaf(hv.w, wreg[4 * kk + 3], a3);
        }
        g_feat[(nb + lbase + j) * HF + tc] = __float2half((a0 + a1) + (a2 + a3));
    }
    for (int i = t; i < 128 * 8; i += 256) {
        int j = i >> 3, c = i & 7;
        int n = nb + j;
        if (n >= N_NODES) continue;
        float s = 0.0f;
#pragma unroll
        for (int k = 0; k < IN_F; k++)
            s = fmaf(hsm[j * IN_F + k], sWlr[k * 8 + c], s);
        if (c < 4) g_el[n * NH + c] = s;
        else       g_er[n * NH + (c - 4)] = s;
    }
}

// ---------------- K2: single-block scan over 50k counts ------------------------
__global__ void __launch_bounds__(1024) k_scan() {
    const int C = (N_NODES + 1023) / 1024;
    int t = threadIdx.x, lane = t & 31, wid = t >> 5;
    int base = t * C;
    int s = 0;
    for (int i = 0; i < C; i++) {
        int idx = base + i;
        if (idx < N_NODES) s += g_cnt[idx];
    }
    int v = s;
#pragma unroll
    for (int o = 1; o < 32; o <<= 1) {
        int n = __shfl_up_sync(0xffffffffu, v, o);
        if (lane >= o) v += n;
    }
    __shared__ int wsum[32];
    if (lane == 31) wsum[wid] = v;
    __syncthreads();
    if (wid == 0) {
        int w = wsum[lane];
#pragma unroll
        for (int o = 1; o < 32; o <<= 1) {
            int n = __shfl_up_sync(0xffffffffu, w, o);
            if (lane >= o) w += n;
        }
        wsum[lane] = w;
    }
    __syncthreads();
    int run = v - s + (wid ? wsum[wid - 1] : 0);
    for (int i = 0; i < C; i++) {
        int idx = base + i;
        if (idx < N_NODES) {
            int c = g_cnt[idx];
            g_rowp[idx] = run;
            g_cnt[idx]  = run;
            run += c;
        }
    }
    if (t == 0) g_rowp[N_NODES] = N_EDGES;
}

// ---------------- K3: CSR fill -------------------------------------------------
__global__ void __launch_bounds__(256) k_fill(
    const void* __restrict__ src, const void* __restrict__ dst)
{
    __shared__ int s64;
    if (threadIdx.x == 0) s64 = probe64(dst);
    __syncthreads();
    int is64 = s64;
    int e = blockIdx.x * blockDim.x + threadIdx.x;
    if (e >= N_EDGES) return;
    int d = is64 ? (int)((const long long*)dst)[e] : ((const int*)dst)[e];
    int s = is64 ? (int)((const long long*)src)[e] : ((const int*)src)[e];
    int pos = atomicAdd(&g_cnt[d], 1);
    g_csrc[pos] = s;
}

// ---------------- K4: aggregate -> writes fp16 GRU input -----------------------
__global__ void __launch_bounds__(256) k_aggr() {
    int n = blockIdx.x * 8 + (threadIdx.x >> 5);
    if (n >= N_NODES) return;
    int lane = threadIdx.x & 31;
    int hd = lane >> 3, sub = lane & 7;
    int beg = g_rowp[n], end = g_rowp[n + 1];
    float er_h = g_er[n * NH + hd];

    float4 acc = make_float4(0.f, 0.f, 0.f, 0.f);
    float dsum = 0.f;
    int gbase = lane & 24;

    for (int base = beg; base < end; base += 32) {
        int cnt = min(32, end - base);
        int sidx = (lane < cnt) ? g_csrc[base + lane] : 0;
        for (int c0 = 0; c0 < cnt; c0 += 8) {
            int ej = c0 + sub;
            int sj_mine = __shfl_sync(0xffffffffu, sidx, ej);
            float ee_mine = (ej < cnt)
                ? __expf(lrelu(g_el[sj_mine * NH + hd] + er_h)) : 0.f;
            dsum += ee_mine;
#pragma unroll
            for (int j = 0; j < 8; j++) {
                float ee = __shfl_sync(0xffffffffu, ee_mine, gbase + j);
                int sj   = __shfl_sync(0xffffffffu, sidx, c0 + j);
                uint2 fv = *(const uint2*)&g_feat[sj * HF + lane * 4];
                float2 fa = __half22float2(*(const __half2*)&fv.x);
                float2 fb = __half22float2(*(const __half2*)&fv.y);
                acc.x = fmaf(fa.x, ee, acc.x);
                acc.y = fmaf(fa.y, ee, acc.y);
                acc.z = fmaf(fb.x, ee, acc.z);
                acc.w = fmaf(fb.y, ee, acc.w);
            }
        }
    }
    dsum += __shfl_xor_sync(0xffffffffu, dsum, 1);
    dsum += __shfl_xor_sync(0xffffffffu, dsum, 2);
    dsum += __shfl_xor_sync(0xffffffffu, dsum, 4);
    float inv = (dsum > 0.f) ? 1.0f / dsum : 0.0f;
    __half2 h0 = __floats2half2_rn(acc.x * inv, acc.y * inv);
    __half2 h1 = __floats2half2_rn(acc.z * inv, acc.w * inv);
    uint2 st; st.x = *(unsigned*)&h0; st.y = *(unsigned*)&h1;
    *(uint2*)&g_xh[n * HF + lane * 4] = st;
}

// ---------------- K5: GRU — wmma fp16 GEMM for gi + scalar Whh path ------------
#define NODES_B 128
#define XLD     136   // fp16 row stride (16B multiple)
#define GILD    104   // fp32 gi row stride
#define WH_PAD  36

__global__ void __launch_bounds__(512) k_gru(
    const float* __restrict__ h, const float* __restrict__ Wih,
    const float* __restrict__ Whh,
    const float* __restrict__ bih, const float* __restrict__ bhh,
    float* __restrict__ out)
{
    extern __shared__ __align__(16) char smraw[];
    float*  sGi  = (float*)smraw;                       // [128][104]
    float*  sH   = sGi + NODES_B * GILD;                // [128][32]
    float*  sWhh = sH + NODES_B * FD;                   // [96][36]
    float*  sbi  = sWhh + G3 * WH_PAD;                  // 96
    float*  sbh  = sbi + G3;                            // 96
    __half* sX   = (__half*)(sbh + G3);                 // [128][136]
    __half* sW   = sX + NODES_B * XLD;                  // [96][136]

    int t = threadIdx.x;
    int base = blockIdx.x * NODES_B;

    // stage x (fp16) rows: 128 rows x 16 uint4
    for (int i = t; i < NODES_B * 16; i += 512) {
        int r = i >> 4, c = i & 15;
        int n = base + r;
        uint4 v = make_uint4(0u, 0u, 0u, 0u);
        if (n < N_NODES) v = ((const uint4*)&g_xh[n * HF])[c];
        *(uint4*)&sX[r * XLD + c * 8] = v;
    }
    // stage Wih: fp32 global -> fp16 smem (convert on the fly)
    for (int i = t; i < G3 * (HF / 4); i += 512) {
        float4 w = ((const float4*)Wih)[i];
        __half2 p0 = __floats2half2_rn(w.x, w.y);
        __half2 p1 = __floats2half2_rn(w.z, w.w);
        int r = i >> 5, c = i & 31;   // HF/4 = 32 float4 per row
        uint2 v; v.x = *(unsigned*)&p0; v.y = *(unsigned*)&p1;
        *(uint2*)&sW[r * XLD + c * 4] = v;
    }
    for (int i = t; i < G3 * FD; i += 512) sWhh[(i >> 5) * WH_PAD + (i & 31)] = Whh[i];
    if (t < G3) { sbi[t] = bih[t]; sbh[t] = bhh[t]; }
    float4 z4 = make_float4(0.f, 0.f, 0.f, 0.f);
    for (int i = t; i < NODES_B * FD / 4; i += 512) {
        int n = base + (i >> 3);
        ((float4*)sH)[i] = (n < N_NODES) ? ((const float4*)h)[n * 8 + (i & 7)] : z4;
    }
    __syncthreads();

    // ---- wmma: 16 warps; warp = (row-tile mt, col-half), 3 of 6 col tiles each
    {
        int wid = t >> 5;
        int mt = wid >> 1, chalf = wid & 1;
        int m0 = mt * 16;
        wmma::fragment<wmma::accumulator, 16, 16, 16, float> acc[3];
#pragma unroll
        for (int c = 0; c < 3; c++) wmma::fill_fragment(acc[c], 0.0f);
#pragma unroll
        for (int k0 = 0; k0 < HF; k0 += 16) {
            wmma::fragment<wmma::matrix_a, 16, 16, 16, __half, wmma::row_major> fa;
            wmma::load_matrix_sync(fa, sX + m0 * XLD + k0, XLD);
#pragma unroll
            for (int c = 0; c < 3; c++) {
                int n0 = (chalf * 3 + c) * 16;
                wmma::fragment<wmma::matrix_b, 16, 16, 16, __half, wmma::col_major> fb;
                wmma::load_matrix_sync(fb, sW + n0 * XLD + k0, XLD);
                wmma::mma_sync(acc[c], fa, fb, acc[c]);
            }
        }
#pragma unroll
        for (int c = 0; c < 3; c++)
            wmma::store_matrix_sync(sGi + m0 * GILD + (chalf * 3 + c) * 16,
                                    acc[c], GILD, wmma::mem_row_major);
    }
    __syncthreads();

    // ---- epilogue: 16 warps, 8 nodes each; oi = lane
    int oi = t & 31, ni = t >> 5;
    float hr[8], hz[8], hn[8];
#pragma unroll
    for (int j = 0; j < 8; j++) {
        hr[j] = sbh[oi]; hz[j] = sbh[32 + oi]; hn[j] = sbh[64 + oi];
    }
    for (int k = 0; k < FD; k += 4) {
        float4 w0 = *(const float4*)&sWhh[oi * WH_PAD + k];
        float4 w1 = *(const float4*)&sWhh[(32 + oi) * WH_PAD + k];
        float4 w2 = *(const float4*)&sWhh[(64 + oi) * WH_PAD + k];
#pragma unroll
        for (int j = 0; j < 8; j++) {
            float4 hv = *(const float4*)&sH[(ni * 8 + j) * FD + k];
            hr[j] = fmaf(w0.x, hv.x, fmaf(w0.y, hv.y, fmaf(w0.z, hv.z, fmaf(w0.w, hv.w, hr[j]))));
            hz[j] = fmaf(w1.x, hv.x, fmaf(w1.y, hv.y, fmaf(w1.z, hv.z, fmaf(w1.w, hv.w, hz[j]))));
            hn[j] = fmaf(w2.x, hv.x, fmaf(w2.y, hv.y, fmaf(w2.z, hv.z, fmaf(w2.w, hv.w, hn[j]))));
        }
    }
#pragma unroll
    for (int j = 0; j < 8; j++) {
        int nl = ni * 8 + j;
        int n = base + nl;
        if (n >= N_NODES) continue;
        float gi_r = sGi[nl * GILD + oi]      + sbi[oi];
        float gi_z = sGi[nl * GILD + 32 + oi] + sbi[32 + oi];
        float gi_n = sGi[nl * GILD + 64 + oi] + sbi[64 + oi];
        // sigmoid(x) = 0.5*tanh(x/2) + 0.5  (1 MUFU instead of exp+rcp)
        float r  = fmaf(0.5f, tanhfast(0.5f * (gi_r + hr[j])), 0.5f);
        float z  = fmaf(0.5f, tanhfast(0.5f * (gi_z + hz[j])), 0.5f);
        float nn = tanhfast(gi_n + r * hn[j]);
        float hv = sH[nl * FD + oi];
        float hnew = (1.0f - z) * nn + z * hv;
        out[n * FD + oi] = hnew > 0.0f ? hnew : (__expf(hnew) - 1.0f);
    }
}

// ---------------- launch -------------------------------------------------------
extern "C" void kernel_launch(void* const* d_in, const int* in_sizes, int n_in,
                              void* d_out, int out_size)
{
    const float* h    = (const float*)d_in[0];
    const float* Wg   = (const float*)d_in[1];
    const float* al   = (const float*)d_in[2];
    const float* ar   = (const float*)d_in[3];
    const float* Wih  = (const float*)d_in[4];
    const float* Whh  = (const float*)d_in[5];
    const float* bih  = (const float*)d_in[6];
    const float* bhh  = (const float*)d_in[7];
    const void*  src  = d_in[8];
    const void*  dst  = d_in[9];
    float* out = (float*)d_out;

    size_t gru_smem = (size_t)(NODES_B * GILD + NODES_B * FD + G3 * WH_PAD + 2 * G3) * 4
                    + (size_t)(NODES_B * XLD + G3 * XLD) * 2;
    static int* cnt_addr = nullptr;
    if (!cnt_addr) {
        cudaFuncSetAttribute(k_gru, cudaFuncAttributeMaxDynamicSharedMemorySize, (int)gru_smem);
        cudaGetSymbolAddress((void**)&cnt_addr, g_cnt);
    }

    cudaMemsetAsync(cnt_addr, 0, N_NODES * sizeof(int), 0);
    int hist_blocks = (N_EDGES + 1023) / 1024;
    k_feathist<<<FEAT_BLOCKS + hist_blocks, 256>>>(h, Wg, al, ar, dst);
    k_scan    <<<1, 1024>>>();
    k_fill    <<<(N_EDGES + 255) / 256, 256>>>(src, dst);
    k_aggr    <<<(N_NODES + 7) / 8, 256>>>();
    k_gru     <<<(N_NODES + NODES_B - 1) / NODES_B, 512, gru_smem>>>(h, Wih, Whh, bih, bhh, out);
}

// round 15
// speedup vs baseline: 1.2958x; 1.2958x over previous
#include <cuda_runtime.h>
#include <cuda_fp16.h>
#include <mma.h>
#include <cstdint>
using namespace nvcuda;

#define N_NODES 50000
#define N_EDGES 800000
#define IN_F    32
#define HF      128   // H*F
#define NH      4
#define FD      32
#define G3      96    // 3*F

// ---------------- scratch (device globals) ------------------------------------
__device__ __align__(16) __half g_feat [N_NODES * HF];  // fp16 gather stream
__device__ __align__(16) float  g_el   [N_NODES * NH];
__device__ __align__(16) float  g_er   [N_NODES * NH];
__device__ __align__(16) __half g_xh   [N_NODES * HF];  // GRU input, fp16
__device__ __align__(16) __half g_Wih16[G3 * HF];       // Wih pre-converted
__device__ __align__(16) float  g_Wl   [IN_F * NH];
__device__ __align__(16) float  g_Wr   [IN_F * NH];
__device__ int g_cnt [N_NODES];
__device__ int g_rowp[N_NODES + 1];
__device__ int g_csrc[N_EDGES];
__device__ int g_idx64;

__device__ __forceinline__ int ldidx(const void* p, int e, int is64) {
    return is64 ? (int)((const long long*)p)[e] : ((const int*)p)[e];
}
__device__ __forceinline__ float lrelu(float x) { return x > 0.f ? x : 0.2f * x; }
__device__ __forceinline__ float tanhfast(float x) {
    float y; asm("tanh.approx.f32 %0, %1;" : "=f"(y) : "f"(x)); return y;
}

// ---------------- K0: probe + zero counters + attn projection + Wih->fp16 ------
__global__ void k_init(const unsigned* __restrict__ raw,
                       const float* __restrict__ Wg,
                       const float* __restrict__ al, const float* __restrict__ ar,
                       const float* __restrict__ Wih) {
    int i = blockIdx.x * blockDim.x + threadIdx.x;
    if (i < N_NODES) g_cnt[i] = 0;
    if (i < G3 * HF) g_Wih16[i] = __float2half(Wih[i]);
    if (blockIdx.x == 0 && threadIdx.x == 0) {
        unsigned any = 0;
#pragma unroll
        for (int k = 1; k < 256; k += 2) any |= raw[k];
        g_idx64 = (any == 0u) ? 1 : 0;
    }
    if (blockIdx.x == 0 && threadIdx.x < IN_F * NH) {
        int k = threadIdx.x >> 2, hh = threadIdx.x & 3;
        float sl = 0.f, sr = 0.f;
#pragma unroll
        for (int f = 0; f < 32; f++) {
            float w = Wg[k * HF + hh * 32 + f];
            sl = fmaf(w, al[hh * 32 + f], sl);
            sr = fmaf(w, ar[hh * 32 + f], sr);
        }
        g_Wl[k * NH + hh] = sl;
        g_Wr[k * NH + hh] = sr;
    }
}

// ---------------- K1: feat-GEMM (reg-cached W col) + el/er + dst histogram -----
#define FEAT_BLOCKS 391   // ceil(50000/128)
__global__ void __launch_bounds__(256) k_feathist(
    const float* __restrict__ h, const float* __restrict__ Wg,
    const void* __restrict__ dst)
{
    __shared__ float hsm[128 * IN_F];   // 16 KB
    __shared__ float sWlr[IN_F * 8];
    int t = threadIdx.x;
    if (blockIdx.x >= FEAT_BLOCKS) {
        int e4 = ((blockIdx.x - FEAT_BLOCKS) * 256 + t) * 4;
        if (e4 >= N_EDGES) return;
        int d0, d1, d2, d3;
        if (g_idx64) {
            longlong2 a = ((const longlong2*)dst)[e4 >> 1];
            longlong2 b = ((const longlong2*)dst)[(e4 >> 1) + 1];
            d0 = (int)a.x; d1 = (int)a.y; d2 = (int)b.x; d3 = (int)b.y;
        } else {
            int4 v = ((const int4*)dst)[e4 >> 2];
            d0 = v.x; d1 = v.y; d2 = v.z; d3 = v.w;
        }
        atomicAdd(&g_cnt[d0], 1); atomicAdd(&g_cnt[d1], 1);
        atomicAdd(&g_cnt[d2], 1); atomicAdd(&g_cnt[d3], 1);
        return;
    }
    int tc = t & 127, half = t >> 7;
    float wreg[IN_F];
#pragma unroll
    for (int k = 0; k < IN_F; k++) wreg[k] = Wg[k * HF + tc];
    if (t < IN_F * 8) {
        int k = t >> 3, c = t & 7;
        sWlr[t] = (c < 4) ? g_Wl[k * NH + c] : g_Wr[k * NH + (c - 4)];
    }
    int nb = blockIdx.x * 128;
    for (int i = t; i < 128 * IN_F; i += 256) {
        int n = nb + (i >> 5);
        hsm[i] = (n < N_NODES) ? h[n * IN_F + (i & 31)] : 0.0f;
    }
    __syncthreads();
    int lbase = half * 64;
    int jmax = min(64, N_NODES - nb - lbase);
    for (int j = 0; j < jmax; j++) {
        const float4* hrow = (const float4*)&hsm[(lbase + j) * IN_F];
        float a0 = 0.f, a1 = 0.f, a2 = 0.f, a3 = 0.f;
#pragma unroll
        for (int kk = 0; kk < IN_F / 4; kk++) {
            float4 hv = hrow[kk];
            a0 = fmaf(hv.x, wreg[4 * kk + 0], a0);
            a1 = fmaf(hv.y, wreg[4 * kk + 1], a1);
            a2 = fmaf(hv.z, wreg[4 * kk + 2], a2);
            a3 = fmaf(hv.w, wreg[4 * kk + 3], a3);
        }
        g_feat[(nb + lbase + j) * HF + tc] = __float2half((a0 + a1) + (a2 + a3));
    }
    for (int i = t; i < 128 * 8; i += 256) {
        int j = i >> 3, c = i & 7;
        int n = nb + j;
        if (n >= N_NODES) continue;
        float s = 0.0f;
#pragma unroll
        for (int k = 0; k < IN_F; k++)
            s = fmaf(hsm[j * IN_F + k], sWlr[k * 8 + c], s);
        if (c < 4) g_el[n * NH + c] = s;
        else       g_er[n * NH + (c - 4)] = s;
    }
}

// ---------------- K2: coalesced tile-wise block scan (49 x 1024) ---------------
__global__ void __launch_bounds__(1024) k_scan() {
    __shared__ int wsum[32];
    __shared__ int carry_s;
    int t = threadIdx.x, lane = t & 31, wid = t >> 5;
    if (t == 0) carry_s = 0;
    __syncthreads();
    const int NT = (N_NODES + 1023) / 1024;   // 49
    for (int it = 0; it < NT; it++) {
        int i = it * 1024 + t;
        int c = (i < N_NODES) ? g_cnt[i] : 0;   // coalesced
        int v = c;
#pragma unroll
        for (int o = 1; o < 32; o <<= 1) {
            int u = __shfl_up_sync(0xffffffffu, v, o);
            if (lane >= o) v += u;
        }
        if (lane == 31) wsum[wid] = v;
        __syncthreads();
        if (wid == 0) {
            int w = wsum[lane];
#pragma unroll
            for (int o = 1; o < 32; o <<= 1) {
                int u = __shfl_up_sync(0xffffffffu, w, o);
                if (lane >= o) w += u;
            }
            wsum[lane] = w;
        }
        __syncthreads();
        int excl = v - c + (wid ? wsum[wid - 1] : 0) + carry_s;
        if (i < N_NODES) { g_rowp[i] = excl; g_cnt[i] = excl; }   // coalesced
        int tile_total = wsum[31];
        __syncthreads();          // everyone has read carry_s & wsum
        if (t == 0) carry_s += tile_total;
        __syncthreads();          // carry updated, wsum free for next tile
    }
    if (t == 0) g_rowp[N_NODES] = N_EDGES;
}

// ---------------- K3: CSR fill -------------------------------------------------
__global__ void __launch_bounds__(256) k_fill(
    const void* __restrict__ src, const void* __restrict__ dst)
{
    int e = blockIdx.x * blockDim.x + threadIdx.x;
    if (e >= N_EDGES) return;
    int is64 = g_idx64;
    int d = ldidx(dst, e, is64);
    int pos = atomicAdd(&g_cnt[d], 1);
    g_csrc[pos] = ldidx(src, e, is64);
}

// ---------------- K4: aggregate -> writes fp16 GRU input -----------------------
__global__ void __launch_bounds__(256) k_aggr() {
    int n = blockIdx.x * 8 + (threadIdx.x >> 5);
    if (n >= N_NODES) return;
    int lane = threadIdx.x & 31;
    int hd = lane >> 3, sub = lane & 7;
    int beg = g_rowp[n], end = g_rowp[n + 1];
    float er_h = g_er[n * NH + hd];

    float4 acc = make_float4(0.f, 0.f, 0.f, 0.f);
    float dsum = 0.f;
    int gbase = lane & 24;

    for (int base = beg; base < end; base += 32) {
        int cnt = min(32, end - base);
        int sidx = (lane < cnt) ? g_csrc[base + lane] : 0;
        for (int c0 = 0; c0 < cnt; c0 += 8) {
            int ej = c0 + sub;
            int sj_mine = __shfl_sync(0xffffffffu, sidx, ej);
            float ee_mine = (ej < cnt)
                ? __expf(lrelu(g_el[sj_mine * NH + hd] + er_h)) : 0.f;
            dsum += ee_mine;
#pragma unroll
            for (int j = 0; j < 8; j++) {
                float ee = __shfl_sync(0xffffffffu, ee_mine, gbase + j);
                int sj   = __shfl_sync(0xffffffffu, sidx, c0 + j);
                uint2 fv = *(const uint2*)&g_feat[sj * HF + lane * 4];
                float2 fa = __half22float2(*(const __half2*)&fv.x);
                float2 fb = __half22float2(*(const __half2*)&fv.y);
                acc.x = fmaf(fa.x, ee, acc.x);
                acc.y = fmaf(fa.y, ee, acc.y);
                acc.z = fmaf(fb.x, ee, acc.z);
                acc.w = fmaf(fb.y, ee, acc.w);
            }
        }
    }
    dsum += __shfl_xor_sync(0xffffffffu, dsum, 1);
    dsum += __shfl_xor_sync(0xffffffffu, dsum, 2);
    dsum += __shfl_xor_sync(0xffffffffu, dsum, 4);
    float inv = (dsum > 0.f) ? 1.0f / dsum : 0.0f;
    __half2 h0 = __floats2half2_rn(acc.x * inv, acc.y * inv);
    __half2 h1 = __floats2half2_rn(acc.z * inv, acc.w * inv);
    uint2 st; st.x = *(unsigned*)&h0; st.y = *(unsigned*)&h1;
    *(uint2*)&g_xh[n * HF + lane * 4] = st;
}

// ---------------- K5: GRU — wmma fp16 GEMM for gi + scalar Whh path ------------
#define NODES_B 128
#define XLD     136   // fp16 row stride (16B multiple)
#define GILD    104   // fp32 gi row stride
#define WH_PAD  36

__global__ void __launch_bounds__(512) k_gru(
    const float* __restrict__ h,
    const float* __restrict__ Whh,
    const float* __restrict__ bih, const float* __restrict__ bhh,
    float* __restrict__ out)
{
    extern __shared__ __align__(16) char smraw[];
    float*  sGi  = (float*)smraw;                       // [128][104]
    float*  sH   = sGi + NODES_B * GILD;                // [128][32]
    float*  sWhh = sH + NODES_B * FD;                   // [96][36]
    float*  sbi  = sWhh + G3 * WH_PAD;                  // 96
    float*  sbh  = sbi + G3;                            // 96
    __half* sX   = (__half*)(sbh + G3);                 // [128][136]
    __half* sW   = sX + NODES_B * XLD;                  // [96][136]

    int t = threadIdx.x;
    int base = blockIdx.x * NODES_B;

    for (int i = t; i < NODES_B * 16; i += 512) {
        int r = i >> 4, c = i & 15;
        int n = base + r;
        uint4 v = make_uint4(0u, 0u, 0u, 0u);
        if (n < N_NODES) v = ((const uint4*)&g_xh[n * HF])[c];
        *(uint4*)&sX[r * XLD + c * 8] = v;
    }
    for (int i = t; i < G3 * 16; i += 512) {
        int r = i >> 4, c = i & 15;
        *(uint4*)&sW[r * XLD + c * 8] = ((const uint4*)&g_Wih16[r * HF])[c];
    }
    for (int i = t; i < G3 * FD; i += 512) sWhh[(i >> 5) * WH_PAD + (i & 31)] = Whh[i];
    if (t < G3) { sbi[t] = bih[t]; sbh[t] = bhh[t]; }
    float4 z4 = make_float4(0.f, 0.f, 0.f, 0.f);
    for (int i = t; i < NODES_B * FD / 4; i += 512) {
        int n = base + (i >> 3);
        ((float4*)sH)[i] = (n < N_NODES) ? ((const float4*)h)[n * 8 + (i & 7)] : z4;
    }
    __syncthreads();

    {
        int wid = t >> 5;
        int mt = wid >> 1, chalf = wid & 1;
        int m0 = mt * 16;
        wmma::fragment<wmma::accumulator, 16, 16, 16, float> acc[3];
#pragma unroll
        for (int c = 0; c < 3; c++) wmma::fill_fragment(acc[c], 0.0f);
#pragma unroll
        for (int k0 = 0; k0 < HF; k0 += 16) {
            wmma::fragment<wmma::matrix_a, 16, 16, 16, __half, wmma::row_major> fa;
            wmma::load_matrix_sync(fa, sX + m0 * XLD + k0, XLD);
#pragma unroll
            for (int c = 0; c < 3; c++) {
                int n0 = (chalf * 3 + c) * 16;
                wmma::fragment<wmma::matrix_b, 16, 16, 16, __half, wmma::col_major> fb;
                wmma::load_matrix_sync(fb, sW + n0 * XLD + k0, XLD);
                wmma::mma_sync(acc[c], fa, fb, acc[c]);
            }
        }
#pragma unroll
        for (int c = 0; c < 3; c++)
            wmma::store_matrix_sync(sGi + m0 * GILD + (chalf * 3 + c) * 16,
                                    acc[c], GILD, wmma::mem_row_major);
    }
    __syncthreads();

    int oi = t & 31, ni = t >> 5;
    float hr[8], hz[8], hn[8];
#pragma unroll
    for (int j = 0; j < 8; j++) {
        hr[j] = sbh[oi]; hz[j] = sbh[32 + oi]; hn[j] = sbh[64 + oi];
    }
    for (int k = 0; k < FD; k += 4) {
        float4 w0 = *(const float4*)&sWhh[oi * WH_PAD + k];
        float4 w1 = *(const float4*)&sWhh[(32 + oi) * WH_PAD + k];
        float4 w2 = *(const float4*)&sWhh[(64 + oi) * WH_PAD + k];
#pragma unroll
        for (int j = 0; j < 8; j++) {
            float4 hv = *(const float4*)&sH[(ni * 8 + j) * FD + k];
            hr[j] = fmaf(w0.x, hv.x, fmaf(w0.y, hv.y, fmaf(w0.z, hv.z, fmaf(w0.w, hv.w, hr[j]))));
            hz[j] = fmaf(w1.x, hv.x, fmaf(w1.y, hv.y, fmaf(w1.z, hv.z, fmaf(w1.w, hv.w, hz[j]))));
            hn[j] = fmaf(w2.x, hv.x, fmaf(w2.y, hv.y, fmaf(w2.z, hv.z, fmaf(w2.w, hv.w, hn[j]))));
        }
    }
#pragma unroll
    for (int j = 0; j < 8; j++) {
        int nl = ni * 8 + j;
        int n = base + nl;
        if (n >= N_NODES) continue;
        float gi_r = sGi[nl * GILD + oi]      + sbi[oi];
        float gi_z = sGi[nl * GILD + 32 + oi] + sbi[32 + oi];
        float gi_n = sGi[nl * GILD + 64 + oi] + sbi[64 + oi];
        float r  = fmaf(0.5f, tanhfast(0.5f * (gi_r + hr[j])), 0.5f);
        float z  = fmaf(0.5f, tanhfast(0.5f * (gi_z + hz[j])), 0.5f);
        float nn = tanhfast(gi_n + r * hn[j]);
        float hv = sH[nl * FD + oi];
        float hnew = (1.0f - z) * nn + z * hv;
        out[n * FD + oi] = hnew > 0.0f ? hnew : (__expf(hnew) - 1.0f);
    }
}

// ---------------- launch -------------------------------------------------------
extern "C" void kernel_launch(void* const* d_in, const int* in_sizes, int n_in,
                              void* d_out, int out_size)
{
    const float* h    = (const float*)d_in[0];
    const float* Wg   = (const float*)d_in[1];
    const float* al   = (const float*)d_in[2];
    const float* ar   = (const float*)d_in[3];
    const float* Wih  = (const float*)d_in[4];
    const float* Whh  = (const float*)d_in[5];
    const float* bih  = (const float*)d_in[6];
    const float* bhh  = (const float*)d_in[7];
    const void*  src  = d_in[8];
    const void*  dst  = d_in[9];
    float* out = (float*)d_out;

    size_t gru_smem = (size_t)(NODES_B * GILD + NODES_B * FD + G3 * WH_PAD + 2 * G3) * 4
                    + (size_t)(NODES_B * XLD + G3 * XLD) * 2;
    static bool attr_set = false;
    if (!attr_set) {
        cudaFuncSetAttribute(k_gru, cudaFuncAttributeMaxDynamicSharedMemorySize, (int)gru_smem);
        attr_set = true;
    }

    int hist_blocks = (N_EDGES + 1023) / 1024;
    k_init    <<<(N_NODES + 255) / 256, 256>>>((const unsigned*)dst, Wg, al, ar, Wih);
    k_feathist<<<FEAT_BLOCKS + hist_blocks, 256>>>(h, Wg, dst);
    k_scan    <<<1, 1024>>>();
    k_fill    <<<(N_EDGES + 255) / 256, 256>>>(src, dst);
    k_aggr    <<<(N_NODES + 7) / 8, 256>>>();
    k_gru     <<<(N_NODES + NODES_B - 1) / NODES_B, 512, gru_smem>>>(h, Whh, bih, bhh, out);
}

// round 16
// speedup vs baseline: 1.3333x; 1.0290x over previous
#include <cuda_runtime.h>
#include <cuda_fp16.h>
#include <mma.h>
#include <cstdint>
using namespace nvcuda;

#define N_NODES 50000
#define N_EDGES 800000
#define IN_F    32
#define HF      128   // H*F
#define NH      4
#define FD      32
#define G3      96
#define KD      160   // combined GEMM K = HF + FD
#define NOUT    128   // combined GEMM N: 64 rz + 32 i_n + 32 h_n

// ---------------- scratch (device globals) ------------------------------------
__device__ __align__(16) __half g_feat [N_NODES * HF];  // fp16 gather stream
__device__ __align__(16) float  g_el   [N_NODES * NH];
__device__ __align__(16) float  g_er   [N_NODES * NH];
__device__ __align__(16) __half g_Wc16 [NOUT * KD];     // combined GRU weights
__device__ __align__(16) float  g_bc   [NOUT];          // combined bias
__device__ __align__(16) float  g_Wl   [IN_F * NH];
__device__ __align__(16) float  g_Wr   [IN_F * NH];
__device__ int g_cnt [N_NODES];
__device__ int g_rowp[N_NODES + 1];
__device__ int g_csrc[N_EDGES];
__device__ int g_idx64;

__device__ __forceinline__ int ldidx(const void* p, int e, int is64) {
    return is64 ? (int)((const long long*)p)[e] : ((const int*)p)[e];
}
__device__ __forceinline__ float lrelu(float x) { return x > 0.f ? x : 0.2f * x; }
__device__ __forceinline__ float tanhfast(float x) {
    float y; asm("tanh.approx.f32 %0, %1;" : "=f"(y) : "f"(x)); return y;
}

// ---------------- K0: probe + zero + attn projection + combined GRU weights ----
__global__ void k_init(const unsigned* __restrict__ raw,
                       const float* __restrict__ Wg,
                       const float* __restrict__ al, const float* __restrict__ ar,
                       const float* __restrict__ Wih, const float* __restrict__ Whh,
                       const float* __restrict__ bih, const float* __restrict__ bhh) {
    int i = blockIdx.x * blockDim.x + threadIdx.x;
    if (i < N_NODES) g_cnt[i] = 0;
    if (i < NOUT * KD) {
        int c = i / KD, k = i % KD;
        float v;
        if (c < 64)      v = (k < HF) ? Wih[c * HF + k] : Whh[c * FD + (k - HF)];
        else if (c < 96) v = (k < HF) ? Wih[c * HF + k] : 0.f;
        else             v = (k < HF) ? 0.f : Whh[(c - 32) * FD + (k - HF)];
        g_Wc16[i] = __float2half(v);
    }
    if (i < NOUT)
        g_bc[i] = (i < 64) ? bih[i] + bhh[i] : (i < 96 ? bih[i] : bhh[i - 32]);
    if (blockIdx.x == 0 && threadIdx.x == 0) {
        unsigned any = 0;
#pragma unroll
        for (int k = 1; k < 256; k += 2) any |= raw[k];
        g_idx64 = (any == 0u) ? 1 : 0;
    }
    if (blockIdx.x == 0 && threadIdx.x < IN_F * NH) {
        int k = threadIdx.x >> 2, hh = threadIdx.x & 3;
        float sl = 0.f, sr = 0.f;
#pragma unroll
        for (int f = 0; f < 32; f++) {
            float w = Wg[k * HF + hh * 32 + f];
            sl = fmaf(w, al[hh * 32 + f], sl);
            sr = fmaf(w, ar[hh * 32 + f], sr);
        }
        g_Wl[k * NH + hh] = sl;
        g_Wr[k * NH + hh] = sr;
    }
}

// ---------------- K1: feat-GEMM (reg-cached W col) + el/er + dst histogram -----
#define FEAT_BLOCKS 391
__global__ void __launch_bounds__(256) k_feathist(
    const float* __restrict__ h, const float* __restrict__ Wg,
    const void* __restrict__ dst)
{
    __shared__ float hsm[128 * IN_F];
    __shared__ float sWlr[IN_F * 8];
    int t = threadIdx.x;
    if (blockIdx.x >= FEAT_BLOCKS) {
        int e4 = ((blockIdx.x - FEAT_BLOCKS) * 256 + t) * 4;
        if (e4 >= N_EDGES) return;
        int d0, d1, d2, d3;
        if (g_idx64) {
            longlong2 a = ((const longlong2*)dst)[e4 >> 1];
            longlong2 b = ((const longlong2*)dst)[(e4 >> 1) + 1];
            d0 = (int)a.x; d1 = (int)a.y; d2 = (int)b.x; d3 = (int)b.y;
        } else {
            int4 v = ((const int4*)dst)[e4 >> 2];
            d0 = v.x; d1 = v.y; d2 = v.z; d3 = v.w;
        }
        atomicAdd(&g_cnt[d0], 1); atomicAdd(&g_cnt[d1], 1);
        atomicAdd(&g_cnt[d2], 1); atomicAdd(&g_cnt[d3], 1);
        return;
    }
    int tc = t & 127, half = t >> 7;
    float wreg[IN_F];
#pragma unroll
    for (int k = 0; k < IN_F; k++) wreg[k] = Wg[k * HF + tc];
    if (t < IN_F * 8) {
        int k = t >> 3, c = t & 7;
        sWlr[t] = (c < 4) ? g_Wl[k * NH + c] : g_Wr[k * NH + (c - 4)];
    }
    int nb = blockIdx.x * 128;
    for (int i = t; i < 128 * IN_F; i += 256) {
        int n = nb + (i >> 5);
        hsm[i] = (n < N_NODES) ? h[n * IN_F + (i & 31)] : 0.0f;
    }
    __syncthreads();
    int lbase = half * 64;
    int jmax = min(64, N_NODES - nb - lbase);
    for (int j = 0; j < jmax; j++) {
        const float4* hrow = (const float4*)&hsm[(lbase + j) * IN_F];
        float a0 = 0.f, a1 = 0.f, a2 = 0.f, a3 = 0.f;
#pragma unroll
        for (int kk = 0; kk < IN_F / 4; kk++) {
            float4 hv = hrow[kk];
            a0 = fmaf(hv.x, wreg[4 * kk + 0], a0);
            a1 = fmaf(hv.y, wreg[4 * kk + 1], a1);
            a2 = fmaf(hv.z, wreg[4 * kk + 2], a2);
            a3 = fmaf(hv.w, wreg[4 * kk + 3], a3);
        }
        g_feat[(nb + lbase + j) * HF + tc] = __float2half((a0 + a1) + (a2 + a3));
    }
    for (int i = t; i < 128 * 8; i += 256) {
        int j = i >> 3, c = i & 7;
        int n = nb + j;
        if (n >= N_NODES) continue;
        float s = 0.0f;
#pragma unroll
        for (int k = 0; k < IN_F; k++)
            s = fmaf(hsm[j * IN_F + k], sWlr[k * 8 + c], s);
        if (c < 4) g_el[n * NH + c] = s;
        else       g_er[n * NH + (c - 4)] = s;
    }
}

// ---------------- K2: coalesced tile-wise block scan ---------------------------
__global__ void __launch_bounds__(1024) k_scan() {
    __shared__ int wsum[32];
    __shared__ int carry_s;
    int t = threadIdx.x, lane = t & 31, wid = t >> 5;
    if (t == 0) carry_s = 0;
    __syncthreads();
    const int NT = (N_NODES + 1023) / 1024;
    for (int it = 0; it < NT; it++) {
        int i = it * 1024 + t;
        int c = (i < N_NODES) ? g_cnt[i] : 0;
        int v = c;
#pragma unroll
        for (int o = 1; o < 32; o <<= 1) {
            int u = __shfl_up_sync(0xffffffffu, v, o);
            if (lane >= o) v += u;
        }
        if (lane == 31) wsum[wid] = v;
        __syncthreads();
        if (wid == 0) {
            int w = wsum[lane];
#pragma unroll
            for (int o = 1; o < 32; o <<= 1) {
                int u = __shfl_up_sync(0xffffffffu, w, o);
                if (lane >= o) w += u;
            }
            wsum[lane] = w;
        }
        __syncthreads();
        int excl = v - c + (wid ? wsum[wid - 1] : 0) + carry_s;
        if (i < N_NODES) { g_rowp[i] = excl; g_cnt[i] = excl; }
        int tile_total = wsum[31];
        __syncthreads();
        if (t == 0) carry_s += tile_total;
        __syncthreads();
    }
    if (t == 0) g_rowp[N_NODES] = N_EDGES;
}

// ---------------- K3: CSR fill -------------------------------------------------
__global__ void __launch_bounds__(256) k_fill(
    const void* __restrict__ src, const void* __restrict__ dst)
{
    int e = blockIdx.x * blockDim.x + threadIdx.x;
    if (e >= N_EDGES) return;
    int is64 = g_idx64;
    int d = ldidx(dst, e, is64);
    int pos = atomicAdd(&g_cnt[d], 1);
    g_csrc[pos] = ldidx(src, e, is64);
}

// ---------------- K4: FUSED aggregate + GRU (one wmma GEMM, K=160) -------------
#define NB2  128   // nodes per block
#define XLD2 168   // fp16 [x|h] row stride (160 + 8 pad)
#define OLD  132   // fp32 output row stride

__global__ void __launch_bounds__(512) k_agru(
    const float* __restrict__ h, float* __restrict__ out)
{
    extern __shared__ __align__(16) char smraw[];
    __half* sX = (__half*)smraw;                 // [128][168]  (cols 0-127 x, 128-159 h)
    __half* sW = sX + NB2 * XLD2;                // [128][168]  combined weights (K-major)
    float*  sb = (float*)(sW + NB2 * XLD2);      // 128 combined bias
    float*  sOut = (float*)smraw;                // [128][132] reuses sX/sW after GEMM

    int t = threadIdx.x, lane = t & 31, wrp = t >> 5;
    int base = blockIdx.x * NB2;

    // stage combined weights: flat 2560 uint4
    for (int i = t; i < NOUT * (KD / 8); i += 512) {
        int r = i / 20, c = i % 20;
        *(uint4*)&sW[r * XLD2 + c * 8] = ((const uint4*)g_Wc16)[i];
    }
    if (t < NOUT) sb[t] = g_bc[t];
    // stage h (fp32->fp16) into sX cols 128..159
    for (int i = t; i < NB2 * (FD / 4); i += 512) {
        int r = i >> 3, c = i & 7;
        int n = base + r;
        float4 hv = make_float4(0.f, 0.f, 0.f, 0.f);
        if (n < N_NODES) hv = ((const float4*)h)[n * 8 + c];
        __half2 p0 = __floats2half2_rn(hv.x, hv.y);
        __half2 p1 = __floats2half2_rn(hv.z, hv.w);
        uint2 v; v.x = *(unsigned*)&p0; v.y = *(unsigned*)&p1;
        *(uint2*)&sX[r * XLD2 + HF + c * 4] = v;
    }

    // ---- aggr phase: warp wrp processes nodes base+wrp*8 .. +7
    int hd = lane >> 3, sub = lane & 7, gbase = lane & 24;
    for (int jj = 0; jj < 8; jj++) {
        int nl = wrp * 8 + jj;
        int n = base + nl;
        uint2 st = make_uint2(0u, 0u);
        if (n < N_NODES) {
            int beg = g_rowp[n], end = g_rowp[n + 1];
            float er_h = g_er[n * NH + hd];
            float4 acc = make_float4(0.f, 0.f, 0.f, 0.f);
            float dsum = 0.f;
            for (int b2 = beg; b2 < end; b2 += 32) {
                int cnt = min(32, end - b2);
                int sidx = (lane < cnt) ? g_csrc[b2 + lane] : 0;
                for (int c0 = 0; c0 < cnt; c0 += 8) {
                    int ej = c0 + sub;
                    int sj_mine = __shfl_sync(0xffffffffu, sidx, ej);
                    float ee_mine = (ej < cnt)
                        ? __expf(lrelu(g_el[sj_mine * NH + hd] + er_h)) : 0.f;
                    dsum += ee_mine;
#pragma unroll
                    for (int j = 0; j < 8; j++) {
                        float ee = __shfl_sync(0xffffffffu, ee_mine, gbase + j);
                        int sj   = __shfl_sync(0xffffffffu, sidx, c0 + j);
                        uint2 fv = *(const uint2*)&g_feat[sj * HF + lane * 4];
                        float2 fa = __half22float2(*(const __half2*)&fv.x);
                        float2 fb = __half22float2(*(const __half2*)&fv.y);
                        acc.x = fmaf(fa.x, ee, acc.x);
                        acc.y = fmaf(fa.y, ee, acc.y);
                        acc.z = fmaf(fb.x, ee, acc.z);
                        acc.w = fmaf(fb.y, ee, acc.w);
                    }
                }
            }
            dsum += __shfl_xor_sync(0xffffffffu, dsum, 1);
            dsum += __shfl_xor_sync(0xffffffffu, dsum, 2);
            dsum += __shfl_xor_sync(0xffffffffu, dsum, 4);
            float inv = (dsum > 0.f) ? 1.0f / dsum : 0.0f;
            __half2 h0 = __floats2half2_rn(acc.x * inv, acc.y * inv);
            __half2 h1 = __floats2half2_rn(acc.z * inv, acc.w * inv);
            st.x = *(unsigned*)&h0; st.y = *(unsigned*)&h1;
        }
        *(uint2*)&sX[nl * XLD2 + lane * 4] = st;
    }
    __syncthreads();

    // ---- wmma GEMM: 128x128x160; warp = (mt = wrp>>1, 4 col tiles)
    wmma::fragment<wmma::accumulator, 16, 16, 16, float> acc[4];
    int mt = wrp >> 1, cg = wrp & 1;
    int m0 = mt * 16;
#pragma unroll
    for (int c = 0; c < 4; c++) wmma::fill_fragment(acc[c], 0.0f);
#pragma unroll
    for (int k0 = 0; k0 < KD; k0 += 16) {
        wmma::fragment<wmma::matrix_a, 16, 16, 16, __half, wmma::row_major> fa;
        wmma::load_matrix_sync(fa, sX + m0 * XLD2 + k0, XLD2);
#pragma unroll
        for (int c = 0; c < 4; c++) {
            int n0 = (cg * 4 + c) * 16;
            wmma::fragment<wmma::matrix_b, 16, 16, 16, __half, wmma::col_major> fb;
            wmma::load_matrix_sync(fb, sW + n0 * XLD2 + k0, XLD2);
            wmma::mma_sync(acc[c], fa, fb, acc[c]);
        }
    }
    __syncthreads();   // all warps done reading sX/sW; safe to overwrite with sOut
#pragma unroll
    for (int c = 0; c < 4; c++)
        wmma::store_matrix_sync(sOut + m0 * OLD + (cg * 4 + c) * 16,
                                acc[c], OLD, wmma::mem_row_major);
    __syncthreads();

    // ---- elementwise epilogue: warp wrp -> 8 nodes, lane = output feature
#pragma unroll
    for (int j = 0; j < 8; j++) {
        int nl = wrp * 8 + j;
        int n = base + nl;
        if (n >= N_NODES) continue;
        float rp  = sOut[nl * OLD + lane]       + sb[lane];
        float zp  = sOut[nl * OLD + 32 + lane]  + sb[32 + lane];
        float inp = sOut[nl * OLD + 64 + lane]  + sb[64 + lane];
        float hnp = sOut[nl * OLD + 96 + lane]  + sb[96 + lane];
        float r  = fmaf(0.5f, tanhfast(0.5f * rp), 0.5f);
        float z  = fmaf(0.5f, tanhfast(0.5f * zp), 0.5f);
        float nn = tanhfast(fmaf(r, hnp, inp));
        float hv = h[n * FD + lane];
        float hnew = (1.0f - z) * nn + z * hv;
        out[n * FD + lane] = hnew > 0.0f ? hnew : (__expf(hnew) - 1.0f);
    }
}

// ---------------- launch -------------------------------------------------------
extern "C" void kernel_launch(void* const* d_in, const int* in_sizes, int n_in,
                              void* d_out, int out_size)
{
    const float* h    = (const float*)d_in[0];
    const float* Wg   = (const float*)d_in[1];
    const float* al   = (const float*)d_in[2];
    const float* ar   = (const float*)d_in[3];
    const float* Wih  = (const float*)d_in[4];
    const float* Whh  = (const float*)d_in[5];
    const float* bih  = (const float*)d_in[6];
    const float* bhh  = (const float*)d_in[7];
    const void*  src  = d_in[8];
    const void*  dst  = d_in[9];
    float* out = (float*)d_out;

    size_t agru_smem = (size_t)(2 * NB2 * XLD2) * 2 + NOUT * 4;   // 86528 B
    static bool attr_set = false;
    if (!attr_set) {
        cudaFuncSetAttribute(k_agru, cudaFuncAttributeMaxDynamicSharedMemorySize,
                             (int)agru_smem);
        attr_set = true;
    }

    int hist_blocks = (N_EDGES + 1023) / 1024;
    k_init    <<<(N_NODES + 255) / 256, 256>>>((const unsigned*)dst, Wg, al, ar,
                                               Wih, Whh, bih, bhh);
    k_feathist<<<FEAT_BLOCKS + hist_blocks, 256>>>(h, Wg, dst);
    k_scan    <<<1, 1024>>>();
    k_fill    <<<(N_EDGES + 255) / 256, 256>>>(src, dst);
    k_agru    <<<(N_NODES + NB2 - 1) / NB2, 512, agru_smem>>>(h, out);
}

// round 17
// speedup vs baseline: 1.5768x; 1.1826x over previous
#include <cuda_runtime.h>
#include <cuda_fp16.h>
#include <mma.h>
#include <cstdint>
using namespace nvcuda;

#define N_NODES 50000
#define N_EDGES 800000
#define IN_F    32
#define HF      128   // H*F
#define NH      4
#define FD      32
#define G3      96
#define KD      160   // combined GEMM K = HF + FD
#define NOUT    128   // combined GEMM N: 64 rz + 32 i_n + 32 h_n

// ---------------- scratch (device globals) ------------------------------------
__device__ __align__(16) __half g_feat [N_NODES * HF];  // fp16 gather stream
__device__ __align__(16) float  g_el   [N_NODES * NH];
__device__ __align__(16) float  g_er   [N_NODES * NH];
__device__ __align__(16) __half g_xh   [N_NODES * HF];  // GRU input, fp16
__device__ __align__(16) __half g_Wc16 [NOUT * KD];     // combined GRU weights
__device__ __align__(16) float  g_bc   [NOUT];          // combined bias
__device__ __align__(16) float  g_Wl   [IN_F * NH];
__device__ __align__(16) float  g_Wr   [IN_F * NH];
__device__ int g_cnt [N_NODES];
__device__ int g_rowp[N_NODES + 1];
__device__ int g_csrc[N_EDGES];
__device__ int g_idx64;

__device__ __forceinline__ int ldidx(const void* p, int e, int is64) {
    return is64 ? (int)((const long long*)p)[e] : ((const int*)p)[e];
}
__device__ __forceinline__ float lrelu(float x) { return x > 0.f ? x : 0.2f * x; }
__device__ __forceinline__ float tanhfast(float x) {
    float y; asm("tanh.approx.f32 %0, %1;" : "=f"(y) : "f"(x)); return y;
}

// ---------------- K0: probe + zero + attn projection + combined GRU weights ----
__global__ void k_init(const unsigned* __restrict__ raw,
                       const float* __restrict__ Wg,
                       const float* __restrict__ al, const float* __restrict__ ar,
                       const float* __restrict__ Wih, const float* __restrict__ Whh,
                       const float* __restrict__ bih, const float* __restrict__ bhh) {
    int i = blockIdx.x * blockDim.x + threadIdx.x;
    if (i < N_NODES) g_cnt[i] = 0;
    if (i < NOUT * KD) {
        int c = i / KD, k = i % KD;
        float v;
        if (c < 64)      v = (k < HF) ? Wih[c * HF + k] : Whh[c * FD + (k - HF)];
        else if (c < 96) v = (k < HF) ? Wih[c * HF + k] : 0.f;
        else             v = (k < HF) ? 0.f : Whh[(c - 32) * FD + (k - HF)];
        g_Wc16[i] = __float2half(v);
    }
    if (i < NOUT)
        g_bc[i] = (i < 64) ? bih[i] + bhh[i] : (i < 96 ? bih[i] : bhh[i - 32]);
    if (blockIdx.x == 0 && threadIdx.x == 0) {
        unsigned any = 0;
#pragma unroll
        for (int k = 1; k < 256; k += 2) any |= raw[k];
        g_idx64 = (any == 0u) ? 1 : 0;
    }
    if (blockIdx.x == 0 && threadIdx.x < IN_F * NH) {
        int k = threadIdx.x >> 2, hh = threadIdx.x & 3;
        float sl = 0.f, sr = 0.f;
#pragma unroll
        for (int f = 0; f < 32; f++) {
            float w = Wg[k * HF + hh * 32 + f];
            sl = fmaf(w, al[hh * 32 + f], sl);
            sr = fmaf(w, ar[hh * 32 + f], sr);
        }
        g_Wl[k * NH + hh] = sl;
        g_Wr[k * NH + hh] = sr;
    }
}

// ---------------- K1a: feat-GEMM (reg-cached W col) + el/er — side stream ------
#define FEAT_BLOCKS 391
__global__ void __launch_bounds__(256) k_feat(
    const float* __restrict__ h, const float* __restrict__ Wg)
{
    __shared__ float hsm[128 * IN_F];
    __shared__ float sWlr[IN_F * 8];
    int t = threadIdx.x;
    int tc = t & 127, half = t >> 7;
    float wreg[IN_F];
#pragma unroll
    for (int k = 0; k < IN_F; k++) wreg[k] = Wg[k * HF + tc];
    if (t < IN_F * 8) {
        int k = t >> 3, c = t & 7;
        sWlr[t] = (c < 4) ? g_Wl[k * NH + c] : g_Wr[k * NH + (c - 4)];
    }
    int nb = blockIdx.x * 128;
    for (int i = t; i < 128 * IN_F; i += 256) {
        int n = nb + (i >> 5);
        hsm[i] = (n < N_NODES) ? h[n * IN_F + (i & 31)] : 0.0f;
    }
    __syncthreads();
    int lbase = half * 64;
    int jmax = min(64, N_NODES - nb - lbase);
    for (int j = 0; j < jmax; j++) {
        const float4* hrow = (const float4*)&hsm[(lbase + j) * IN_F];
        float a0 = 0.f, a1 = 0.f, a2 = 0.f, a3 = 0.f;
#pragma unroll
        for (int kk = 0; kk < IN_F / 4; kk++) {
            float4 hv = hrow[kk];
            a0 = fmaf(hv.x, wreg[4 * kk + 0], a0);
            a1 = fmaf(hv.y, wreg[4 * kk + 1], a1);
            a2 = fmaf(hv.z, wreg[4 * kk + 2], a2);
            a3 = fmaf(hv.w, wreg[4 * kk + 3], a3);
        }
        g_feat[(nb + lbase + j) * HF + tc] = __float2half((a0 + a1) + (a2 + a3));
    }
    for (int i = t; i < 128 * 8; i += 256) {
        int j = i >> 3, c = i & 7;
        int n = nb + j;
        if (n >= N_NODES) continue;
        float s = 0.0f;
#pragma unroll
        for (int k = 0; k < IN_F; k++)
            s = fmaf(hsm[j * IN_F + k], sWlr[k * 8 + c], s);
        if (c < 4) g_el[n * NH + c] = s;
        else       g_er[n * NH + (c - 4)] = s;
    }
}

// ---------------- K1b: dst histogram (main stream) -----------------------------
__global__ void __launch_bounds__(256) k_hist(const void* __restrict__ dst) {
    int e4 = (blockIdx.x * 256 + threadIdx.x) * 4;
    if (e4 >= N_EDGES) return;
    int d0, d1, d2, d3;
    if (g_idx64) {
        longlong2 a = ((const longlong2*)dst)[e4 >> 1];
        longlong2 b = ((const longlong2*)dst)[(e4 >> 1) + 1];
        d0 = (int)a.x; d1 = (int)a.y; d2 = (int)b.x; d3 = (int)b.y;
    } else {
        int4 v = ((const int4*)dst)[e4 >> 2];
        d0 = v.x; d1 = v.y; d2 = v.z; d3 = v.w;
    }
    atomicAdd(&g_cnt[d0], 1); atomicAdd(&g_cnt[d1], 1);
    atomicAdd(&g_cnt[d2], 1); atomicAdd(&g_cnt[d3], 1);
}

// ---------------- K2: coalesced tile-wise block scan ---------------------------
__global__ void __launch_bounds__(1024) k_scan() {
    __shared__ int wsum[32];
    __shared__ int carry_s;
    int t = threadIdx.x, lane = t & 31, wid = t >> 5;
    if (t == 0) carry_s = 0;
    __syncthreads();
    const int NT = (N_NODES + 1023) / 1024;
    for (int it = 0; it < NT; it++) {
        int i = it * 1024 + t;
        int c = (i < N_NODES) ? g_cnt[i] : 0;
        int v = c;
#pragma unroll
        for (int o = 1; o < 32; o <<= 1) {
            int u = __shfl_up_sync(0xffffffffu, v, o);
            if (lane >= o) v += u;
        }
        if (lane == 31) wsum[wid] = v;
        __syncthreads();
        if (wid == 0) {
            int w = wsum[lane];
#pragma unroll
            for (int o = 1; o < 32; o <<= 1) {
                int u = __shfl_up_sync(0xffffffffu, w, o);
                if (lane >= o) w += u;
            }
            wsum[lane] = w;
        }
        __syncthreads();
        int excl = v - c + (wid ? wsum[wid - 1] : 0) + carry_s;
        if (i < N_NODES) { g_rowp[i] = excl; g_cnt[i] = excl; }
        int tile_total = wsum[31];
        __syncthreads();
        if (t == 0) carry_s += tile_total;
        __syncthreads();
    }
    if (t == 0) g_rowp[N_NODES] = N_EDGES;
}

// ---------------- K3: CSR fill -------------------------------------------------
__global__ void __launch_bounds__(256) k_fill(
    const void* __restrict__ src, const void* __restrict__ dst)
{
    int e = blockIdx.x * blockDim.x + threadIdx.x;
    if (e >= N_EDGES) return;
    int is64 = g_idx64;
    int d = ldidx(dst, e, is64);
    int pos = atomicAdd(&g_cnt[d], 1);
    g_csrc[pos] = ldidx(src, e, is64);
}

// ---------------- K4: aggregate (standalone, high-occ) -> fp16 GRU input -------
__global__ void __launch_bounds__(256) k_aggr() {
    int n = blockIdx.x * 8 + (threadIdx.x >> 5);
    if (n >= N_NODES) return;
    int lane = threadIdx.x & 31;
    int hd = lane >> 3, sub = lane & 7, gbase = lane & 24;
    int beg = g_rowp[n], end = g_rowp[n + 1];
    float er_h = g_er[n * NH + hd];

    float4 acc = make_float4(0.f, 0.f, 0.f, 0.f);
    float dsum = 0.f;
    for (int base = beg; base < end; base += 32) {
        int cnt = min(32, end - base);
        int sidx = (lane < cnt) ? g_csrc[base + lane] : 0;
        for (int c0 = 0; c0 < cnt; c0 += 8) {
            int ej = c0 + sub;
            int sj_mine = __shfl_sync(0xffffffffu, sidx, ej);
            float ee_mine = (ej < cnt)
                ? __expf(lrelu(g_el[sj_mine * NH + hd] + er_h)) : 0.f;
            dsum += ee_mine;
#pragma unroll
            for (int j = 0; j < 8; j++) {
                float ee = __shfl_sync(0xffffffffu, ee_mine, gbase + j);
                int sj   = __shfl_sync(0xffffffffu, sidx, c0 + j);
                uint2 fv = *(const uint2*)&g_feat[sj * HF + lane * 4];
                float2 fa = __half22float2(*(const __half2*)&fv.x);
                float2 fb = __half22float2(*(const __half2*)&fv.y);
                acc.x = fmaf(fa.x, ee, acc.x);
                acc.y = fmaf(fa.y, ee, acc.y);
                acc.z = fmaf(fb.x, ee, acc.z);
                acc.w = fmaf(fb.y, ee, acc.w);
            }
        }
    }
    dsum += __shfl_xor_sync(0xffffffffu, dsum, 1);
    dsum += __shfl_xor_sync(0xffffffffu, dsum, 2);
    dsum += __shfl_xor_sync(0xffffffffu, dsum, 4);
    float inv = (dsum > 0.f) ? 1.0f / dsum : 0.0f;
    __half2 h0 = __floats2half2_rn(acc.x * inv, acc.y * inv);
    __half2 h1 = __floats2half2_rn(acc.z * inv, acc.w * inv);
    uint2 st; st.x = *(unsigned*)&h0; st.y = *(unsigned*)&h1;
    *(uint2*)&g_xh[n * HF + lane * 4] = st;
}

// ---------------- K5: GRU — ONE combined wmma GEMM (128x128x160) + epilogue ----
#define NB2  128
#define XLD2 168   // fp16 [x|h] row stride
#define OLD  132   // fp32 output row stride

__global__ void __launch_bounds__(512) k_gru(
    const float* __restrict__ h, float* __restrict__ out)
{
    extern __shared__ __align__(16) char smraw[];
    __half* sX = (__half*)smraw;                 // [128][168]
    __half* sW = sX + NB2 * XLD2;                // [128][168]
    float*  sb = (float*)(sW + NB2 * XLD2);      // 128
    float*  sOut = (float*)smraw;                // [128][132] reuse after GEMM

    int t = threadIdx.x, lane = t & 31, wrp = t >> 5;
    int base = blockIdx.x * NB2;

    // stage x cols 0..127 from g_xh
    for (int i = t; i < NB2 * 16; i += 512) {
        int r = i >> 4, c = i & 15;
        int n = base + r;
        uint4 v = make_uint4(0u, 0u, 0u, 0u);
        if (n < N_NODES) v = ((const uint4*)&g_xh[n * HF])[c];
        *(uint4*)&sX[r * XLD2 + c * 8] = v;
    }
    // stage h cols 128..159 (fp32 -> fp16)
    for (int i = t; i < NB2 * 8; i += 512) {
        int r = i >> 3, c = i & 7;
        int n = base + r;
        float4 hv = make_float4(0.f, 0.f, 0.f, 0.f);
        if (n < N_NODES) hv = ((const float4*)h)[n * 8 + c];
        __half2 p0 = __floats2half2_rn(hv.x, hv.y);
        __half2 p1 = __floats2half2_rn(hv.z, hv.w);
        uint2 v; v.x = *(unsigned*)&p0; v.y = *(unsigned*)&p1;
        *(uint2*)&sX[r * XLD2 + HF + c * 4] = v;
    }
    // stage combined weights
    for (int i = t; i < NOUT * (KD / 8); i += 512) {
        int r = i / 20, c = i % 20;
        *(uint4*)&sW[r * XLD2 + c * 8] = ((const uint4*)g_Wc16)[i];
    }
    if (t < NOUT) sb[t] = g_bc[t];
    __syncthreads();

    // wmma: warp (mt, cg) -> rows mt*16, cols (cg*4..cg*4+3)*16
    wmma::fragment<wmma::accumulator, 16, 16, 16, float> acc[4];
    int mt = wrp >> 1, cg = wrp & 1;
    int m0 = mt * 16;
#pragma unroll
    for (int c = 0; c < 4; c++) wmma::fill_fragment(acc[c], 0.0f);
#pragma unroll
    for (int k0 = 0; k0 < KD; k0 += 16) {
        wmma::fragment<wmma::matrix_a, 16, 16, 16, __half, wmma::row_major> fa;
        wmma::load_matrix_sync(fa, sX + m0 * XLD2 + k0, XLD2);
#pragma unroll
        for (int c = 0; c < 4; c++) {
            int n0 = (cg * 4 + c) * 16;
            wmma::fragment<wmma::matrix_b, 16, 16, 16, __half, wmma::col_major> fb;
            wmma::load_matrix_sync(fb, sW + n0 * XLD2 + k0, XLD2);
            wmma::mma_sync(acc[c], fa, fb, acc[c]);
        }
    }
    __syncthreads();   // all reads of sX/sW done before overwrite
#pragma unroll
    for (int c = 0; c < 4; c++)
        wmma::store_matrix_sync(sOut + m0 * OLD + (cg * 4 + c) * 16,
                                acc[c], OLD, wmma::mem_row_major);
    __syncthreads();

#pragma unroll
    for (int j = 0; j < 8; j++) {
        int nl = wrp * 8 + j;
        int n = base + nl;
        if (n >= N_NODES) continue;
        float rp  = sOut[nl * OLD + lane]       + sb[lane];
        float zp  = sOut[nl * OLD + 32 + lane]  + sb[32 + lane];
        float inp = sOut[nl * OLD + 64 + lane]  + sb[64 + lane];
        float hnp = sOut[nl * OLD + 96 + lane]  + sb[96 + lane];
        float r  = fmaf(0.5f, tanhfast(0.5f * rp), 0.5f);
        float z  = fmaf(0.5f, tanhfast(0.5f * zp), 0.5f);
        float nn = tanhfast(fmaf(r, hnp, inp));
        float hv = h[n * FD + lane];
        float hnew = (1.0f - z) * nn + z * hv;
        out[n * FD + lane] = hnew > 0.0f ? hnew : (__expf(hnew) - 1.0f);
    }
}

// ---------------- launch: forked graph (feat on side stream) -------------------
extern "C" void kernel_launch(void* const* d_in, const int* in_sizes, int n_in,
                              void* d_out, int out_size)
{
    const float* h    = (const float*)d_in[0];
    const float* Wg   = (const float*)d_in[1];
    const float* al   = (const float*)d_in[2];
    const float* ar   = (const float*)d_in[3];
    const float* Wih  = (const float*)d_in[4];
    const float* Whh  = (const float*)d_in[5];
    const float* bih  = (const float*)d_in[6];
    const float* bhh  = (const float*)d_in[7];
    const void*  src  = d_in[8];
    const void*  dst  = d_in[9];
    float* out = (float*)d_out;

    size_t gru_smem = (size_t)(2 * NB2 * XLD2) * 2 + NOUT * 4;   // 86528 B
    static cudaStream_t s1 = nullptr;
    static cudaEvent_t evFork, evJoin;
    if (!s1) {
        cudaFuncSetAttribute(k_gru, cudaFuncAttributeMaxDynamicSharedMemorySize,
                             (int)gru_smem);
        cudaStreamCreateWithFlags(&s1, cudaStreamNonBlocking);
        cudaEventCreateWithFlags(&evFork, cudaEventDisableTiming);
        cudaEventCreateWithFlags(&evJoin, cudaEventDisableTiming);
    }

    k_init<<<(N_NODES + 255) / 256, 256>>>((const unsigned*)dst, Wg, al, ar,
                                           Wih, Whh, bih, bhh);
    // fork: feat chain on s1, CSR chain on main stream
    cudaEventRecord(evFork, 0);
    cudaStreamWaitEvent(s1, evFork, 0);
    k_feat<<<FEAT_BLOCKS, 256, 0, s1>>>(h, Wg);
    k_hist<<<(N_EDGES + 1023) / 1024, 256>>>(dst);
    k_scan<<<1, 1024>>>();
    k_fill<<<(N_EDGES + 255) / 256, 256>>>(src, dst);
    // join: aggr needs feat + el/er (s1) and CSR (main)
    cudaEventRecord(evJoin, s1);
    cudaStreamWaitEvent(0, evJoin, 0);
    k_aggr<<<(N_NODES + 7) / 8, 256>>>();
    k_gru <<<(N_NODES + NB2 - 1) / NB2, 512, gru_smem>>>(h, out);
}